// round 16
// baseline (speedup 1.0000x reference)
#include <cuda_runtime.h>
#include <cstdint>

// PackedViterbi (logsumexp semiring) forward — partial-sum exchange.
// theta: [T=256, B=32, S=128, S=128] fp32.  out: [B=32] fp32.
//
// 32 clusters x 4 CTAs; CTA r owns rows AND columns 32r..32r+31. Each step a
// CTA computes partials P[i] = sum_{j in own32} E_t[i,j]*ev[j] for ALL 128 i
// from purely local data, and DSMEM-sends each P[i] (tagged, with a 16-bit
// per-rank scale exponent) to the owner of row i. The receiver's combine of
// 4 packets per own row yields V and the next ev directly — no V broadcast,
// 1 shfl on the chain instead of 3. Scale drift is controlled by a
// self-correcting integer exponent (corr feedback), packets carry the scale.

#define NT   256
#define NB   32
#define NS   128
#define SUBS 4
#define NTHR 256
#define TILE_BYTES (NS * 32 * 4)   // 128 rows x 32 own-cols = 16384 B
#define PIPE 6
#define DIST 4
#define LOG2E 1.4426950408889634f
#define FULLM 0xffffffffu

static __device__ __forceinline__ float ex2f_(float x) {
    float y; asm("ex2.approx.ftz.f32 %0, %1;" : "=f"(y) : "f"(x)); return y;
}
static __device__ __forceinline__ float lg2f_(float x) {
    float y; asm("lg2.approx.ftz.f32 %0, %1;" : "=f"(y) : "f"(x)); return y;
}
static __device__ __forceinline__ void cp16(unsigned d, const void* s) {
    asm volatile("cp.async.cg.shared.global [%0], [%1], 16;" :: "r"(d), "l"(s));
}
static __device__ __forceinline__ void st_dsmem64(unsigned a, unsigned long long v) {
    asm volatile("st.relaxed.cluster.shared::cluster.b64 [%0], %1;"
                 :: "r"(a), "l"(v) : "memory");
}
static __device__ __forceinline__ unsigned long long ld_vol64(unsigned a) {
    unsigned long long v;
    asm volatile("ld.volatile.shared.b64 %0, [%1];" : "=l"(v) : "r"(a));
    return v;
}
static __device__ __forceinline__ float scl_(int d) {   // 2^d for d <= 0
    d = (d < -120) ? -120 : d;
    return __uint_as_float((unsigned)(127 + d) << 23);
}

extern "C" __global__ void __launch_bounds__(NTHR, 1) __cluster_dims__(SUBS, 1, 1)
viterbi_fwd(const float* __restrict__ theta, float* __restrict__ out)
{
    extern __shared__ float4 ring[];                              // PIPE tiles
    __shared__ __align__(16) unsigned long long sP[2][SUBS][32];  // [par][src][row]
    __shared__ __align__(16) float sev[2][32];                    // ev tables
    __shared__ int smsc[2];                                       // packet scale
    __shared__ unsigned long long sT[SUBS];                       // terminal slots

    const int tid  = threadIdx.x;
    const int lane = tid & 31;
    const int warp = tid >> 5;
    const int i    = tid >> 1;          // output row 0..127 (global)
    const int h    = tid & 1;           // which 16 of the 32 own cols
    const int bid  = blockIdx.x;
    const int bb   = bid >> 2;
    const int sub  = bid & 3;

    unsigned rbase = (unsigned)__cvta_generic_to_shared(ring);
    unsigned pbase = (unsigned)__cvta_generic_to_shared(&sP[0][0][0]);
    unsigned tbase = (unsigned)__cvta_generic_to_shared(&sT[0]);

    ((unsigned long long*)sP)[tid] = 0ull;
    if (tid < SUBS) sT[tid] = 0ull;
    if (tid < 2) smsc[tid] = 0;
    __syncthreads();
    asm volatile("barrier.cluster.arrive.aligned;" ::: "memory");
    asm volatile("barrier.cluster.wait.aligned;"   ::: "memory");

    unsigned rp[SUBS], rT0;
#pragma unroll
    for (int r = 0; r < SUBS; ++r)
        asm("mapa.shared::cluster.u32 %0, %1, %2;" : "=r"(rp[r]) : "r"(pbase), "r"(r));
    asm("mapa.shared::cluster.u32 %0, %1, %2;" : "=r"(rT0) : "r"(tbase), "r"(0));

    const size_t tstride = (size_t)NB * NS * NS;
    const float* base = theta + (size_t)bb * NS * NS + sub * 32;   // column slice

    // per-thread copy offsets: chunk c = tid + k*256; row = c>>3, part = c&7
    int srcoff[4], dstoff[4];
#pragma unroll
    for (int k = 0; k < 4; ++k) {
        int c = tid + (k << 8);
        srcoff[k] = (c >> 3) * (NS * 4) + (c & 7) * 16;
        dstoff[k] = c * 16;
    }

    // ---- prologue: prefetch stages 0..DIST-1 ----
#pragma unroll
    for (int s = 0; s < DIST; ++s) {
        const char* src = (const char*)(base + (size_t)s * tstride);
        unsigned dst = rbase + s * TILE_BYTES;
#pragma unroll
        for (int k = 0; k < 4; ++k) cp16(dst + dstoff[k], src + srcoff[k]);
        asm volatile("cp.async.commit_group;");
    }

    float Ea[16], Eb[16];
    int corrCur = 0;

    asm volatile("cp.async.wait_group 3;");
    __syncthreads();
    {   // transform stage 0 -> Ea
        const float4* tp = ring + tid * 4;
        float4 a0 = tp[0], a1 = tp[1], a2 = tp[2], a3 = tp[3];
        Ea[0]=ex2f_(a0.x*LOG2E); Ea[1]=ex2f_(a0.y*LOG2E); Ea[2]=ex2f_(a0.z*LOG2E); Ea[3]=ex2f_(a0.w*LOG2E);
        Ea[4]=ex2f_(a1.x*LOG2E); Ea[5]=ex2f_(a1.y*LOG2E); Ea[6]=ex2f_(a1.z*LOG2E); Ea[7]=ex2f_(a1.w*LOG2E);
        Ea[8]=ex2f_(a2.x*LOG2E); Ea[9]=ex2f_(a2.y*LOG2E); Ea[10]=ex2f_(a2.z*LOG2E); Ea[11]=ex2f_(a2.w*LOG2E);
        Ea[12]=ex2f_(a3.x*LOG2E); Ea[13]=ex2f_(a3.y*LOG2E); Ea[14]=ex2f_(a3.z*LOG2E); Ea[15]=ex2f_(a3.w*LOG2E);
    }

    auto step = [&](int t, int par, float (&Ecur)[16], float (&Enext)[16]) {
        asm volatile("cp.async.wait_group 2;");

        // ---- combine phase (warp 0 only; lane = own row) ----
        if (warp == 0) {
            if (t == 0) {
                sev[0][lane] = 1.f;            // V0 = 0, mscale = 0
            } else {
                unsigned a0 = pbase + (unsigned)(((par * SUBS) * 32 + lane) * 8);
                unsigned P0,T0,P1,T1,P2,T2,P3,T3;
                const unsigned tgt = 4u * (unsigned)t;
                do {
                    asm volatile("ld.volatile.shared.v2.u32 {%0,%1}, [%2];" : "=r"(P0),"=r"(T0) : "r"(a0));
                    asm volatile("ld.volatile.shared.v2.u32 {%0,%1}, [%2];" : "=r"(P1),"=r"(T1) : "r"(a0+256));
                    asm volatile("ld.volatile.shared.v2.u32 {%0,%1}, [%2];" : "=r"(P2),"=r"(T2) : "r"(a0+512));
                    asm volatile("ld.volatile.shared.v2.u32 {%0,%1}, [%2];" : "=r"(P3),"=r"(T3) : "r"(a0+768));
                } while (((T0>>16)+(T1>>16)+(T2>>16)+(T3>>16)) != tgt);
                int m0=(int)(short)(T0&0xFFFFu), m1=(int)(short)(T1&0xFFFFu);
                int m2=(int)(short)(T2&0xFFFFu), m3=(int)(short)(T3&0xFFFFu);
                int mm = max(max(m0,m1), max(m2,m3));
                float S = __uint_as_float(P0)*scl_(m0-mm) + __uint_as_float(P1)*scl_(m1-mm)
                        + __uint_as_float(P2)*scl_(m2-mm) + __uint_as_float(P3)*scl_(m3-mm);
                float lgS = lg2f_(S);
                float delta = lgS - 8.f - (float)corrCur;
                sev[par][lane] = ex2f_(delta);
                if (lane == 0) smsc[par] = mm + 8 + corrCur;
                corrCur = __shfl_sync(FULLM, (int)rintf(delta), 0);
            }
        }
        __syncthreads();

        // ---- dot over own 32 columns (16 per thread), 1 shfl, send ----
        int msc = smsc[par];
        const float4* evp = (const float4*)&sev[par][0] + (h << 2);
        float4 v0 = evp[0], v1 = evp[1], v2 = evp[2], v3 = evp[3];
        float s0 = Ecur[0]*v0.x; s0=fmaf(Ecur[1],v0.y,s0); s0=fmaf(Ecur[2],v0.z,s0); s0=fmaf(Ecur[3],v0.w,s0);
        float s1 = Ecur[4]*v1.x; s1=fmaf(Ecur[5],v1.y,s1); s1=fmaf(Ecur[6],v1.z,s1); s1=fmaf(Ecur[7],v1.w,s1);
        float s2 = Ecur[8]*v2.x; s2=fmaf(Ecur[9],v2.y,s2); s2=fmaf(Ecur[10],v2.z,s2); s2=fmaf(Ecur[11],v2.w,s2);
        float s3 = Ecur[12]*v3.x; s3=fmaf(Ecur[13],v3.y,s3); s3=fmaf(Ecur[14],v3.z,s3); s3=fmaf(Ecur[15],v3.w,s3);
        float P = (s0 + s1) + (s2 + s3);
        P += __shfl_xor_sync(FULLM, P, 1);
        if (h == 0) {
            unsigned hi = ((unsigned)(t + 1) << 16) | ((unsigned)msc & 0xFFFFu);
            unsigned long long pkt = ((unsigned long long)hi << 32)
                                   | (unsigned long long)__float_as_uint(P);
            int rr = i >> 5;
            unsigned daddr = rp[rr]
                + (unsigned)(((((t + 1) & 1) * SUBS + sub) * 32 + (i & 31)) * 8);
            st_dsmem64(daddr, pkt);
        }

        // ---- shadow: prefetch t+DIST, transform t+1 ----
        if (t + DIST < NT) {
            const char* src = (const char*)(base + (size_t)(t + DIST) * tstride);
            unsigned dst = rbase + ((t + DIST) % PIPE) * TILE_BYTES;
#pragma unroll
            for (int k = 0; k < 4; ++k) cp16(dst + dstoff[k], src + srcoff[k]);
        }
        asm volatile("cp.async.commit_group;");

        if (t + 1 < NT) {
            const float4* tp = ring + ((t + 1) % PIPE) * (TILE_BYTES / 16) + tid * 4;
            float4 a0 = tp[0], a1 = tp[1], a2 = tp[2], a3 = tp[3];
            Enext[0]=ex2f_(a0.x*LOG2E); Enext[1]=ex2f_(a0.y*LOG2E); Enext[2]=ex2f_(a0.z*LOG2E); Enext[3]=ex2f_(a0.w*LOG2E);
            Enext[4]=ex2f_(a1.x*LOG2E); Enext[5]=ex2f_(a1.y*LOG2E); Enext[6]=ex2f_(a1.z*LOG2E); Enext[7]=ex2f_(a1.w*LOG2E);
            Enext[8]=ex2f_(a2.x*LOG2E); Enext[9]=ex2f_(a2.y*LOG2E); Enext[10]=ex2f_(a2.z*LOG2E); Enext[11]=ex2f_(a2.w*LOG2E);
            Enext[12]=ex2f_(a3.x*LOG2E); Enext[13]=ex2f_(a3.y*LOG2E); Enext[14]=ex2f_(a3.z*LOG2E); Enext[15]=ex2f_(a3.w*LOG2E);
        }
    };

    for (int t = 0; t < NT; t += 2) {
        step(t,     0, Ea, Eb);
        step(t + 1, 1, Eb, Ea);
    }

    // ---- epilogue: final combine of tag NT (parity 0), terminal reduce ----
    if (warp == 0) {
        unsigned a0 = pbase + (unsigned)(lane * 8);      // par 0, src 0
        unsigned P0,T0,P1,T1,P2,T2,P3,T3;
        const unsigned tgt = 4u * (unsigned)NT;
        do {
            asm volatile("ld.volatile.shared.v2.u32 {%0,%1}, [%2];" : "=r"(P0),"=r"(T0) : "r"(a0));
            asm volatile("ld.volatile.shared.v2.u32 {%0,%1}, [%2];" : "=r"(P1),"=r"(T1) : "r"(a0+256));
            asm volatile("ld.volatile.shared.v2.u32 {%0,%1}, [%2];" : "=r"(P2),"=r"(T2) : "r"(a0+512));
            asm volatile("ld.volatile.shared.v2.u32 {%0,%1}, [%2];" : "=r"(P3),"=r"(T3) : "r"(a0+768));
        } while (((T0>>16)+(T1>>16)+(T2>>16)+(T3>>16)) != tgt);
        int m0=(int)(short)(T0&0xFFFFu), m1=(int)(short)(T1&0xFFFFu);
        int m2=(int)(short)(T2&0xFFFFu), m3=(int)(short)(T3&0xFFFFu);
        int mm = max(max(m0,m1), max(m2,m3));
        float S = __uint_as_float(P0)*scl_(m0-mm) + __uint_as_float(P1)*scl_(m1-mm)
                + __uint_as_float(P2)*scl_(m2-mm) + __uint_as_float(P3)*scl_(m3-mm);
        float lgS = lg2f_(S);
        sev[0][lane] = ex2f_(lgS - 8.f);                 // scale mm + 8
        if (lane == 0) smsc[0] = mm + 8;
    }
    __syncthreads();
    if (warp == 0) {
        float e = sev[0][lane];
#pragma unroll
        for (int o = 16; o; o >>= 1) e += __shfl_xor_sync(FULLM, e, o);
        if (lane == 0) {
            float W = lg2f_(e) + (float)smsc[0];         // log2 of rank-local sum
            unsigned long long pkt =
                ((unsigned long long)(((unsigned)(NT + 1)) << 16) << 32)
                | (unsigned long long)__float_as_uint(W);
            st_dsmem64(rT0 + (unsigned)(sub * 8), pkt);
        }
    }
    if (sub == 0 && tid == 0) {
        float W[4];
#pragma unroll
        for (int q = 0; q < 4; ++q) {
            unsigned long long v;
            unsigned a = tbase + (unsigned)(q * 8);
            do { v = ld_vol64(a); } while ((unsigned)(v >> 48) != (unsigned)(NT + 1));
            W[q] = __uint_as_float((unsigned)v);
        }
        float wm = fmaxf(fmaxf(W[0], W[1]), fmaxf(W[2], W[3]));
        float ss = ex2f_(W[0]-wm) + ex2f_(W[1]-wm) + ex2f_(W[2]-wm) + ex2f_(W[3]-wm);
        out[bb] = 0.6931471805599453f * (wm + lg2f_(ss));
    }
    asm volatile("barrier.cluster.arrive.aligned;" ::: "memory");
    asm volatile("barrier.cluster.wait.aligned;"   ::: "memory");
}

extern "C" void kernel_launch(void* const* d_in, const int* in_sizes, int n_in,
                              void* d_out, int out_size)
{
    (void)in_sizes; (void)n_in; (void)out_size;
    const float* theta = (const float*)d_in[0];
    float* out = (float*)d_out;

    cudaFuncSetAttribute(viterbi_fwd,
                         cudaFuncAttributeMaxDynamicSharedMemorySize,
                         PIPE * TILE_BYTES);
    viterbi_fwd<<<NB * SUBS, NTHR, PIPE * TILE_BYTES>>>(theta, out);
}